// round 2
// baseline (speedup 1.0000x reference)
#include <cuda_runtime.h>
#include <math.h>

#define B_ 8
#define T_ 2048
#define D_ 768
#define BM 64
#define BN 64
#define BK 16

// Scratch: scores -> (in-place) weights. 8*2048*2048 floats = 134 MB, static device bss.
__device__ float g_S[(size_t)B_ * T_ * T_];

// ---------------------------------------------------------------------------
// Kernel 1: S[b,i,j] = dot(X[b,i,:], X[b,j,:]) / sqrt(D)  (lower-triangle tiles only)
// ---------------------------------------------------------------------------
__global__ __launch_bounds__(256) void qk_kernel(const float* __restrict__ X) {
    int b  = blockIdx.z;
    int i0 = blockIdx.y * BM;
    int j0 = blockIdx.x * BN;
    if (j0 > i0) return;  // tile entirely above diagonal -> never read by softmax

    const float* A = X + (size_t)b * T_ * D_;
    float* C = g_S + (size_t)b * T_ * T_;

    __shared__ float As[BK][BM];
    __shared__ float Bs[BK][BN];

    int tid = threadIdx.x;
    int ty = tid >> 4, tx = tid & 15;
    int lr = tid >> 2;            // 0..63
    int lk = (tid & 3) << 2;      // 0,4,8,12

    float acc[4][4];
#pragma unroll
    for (int r = 0; r < 4; r++)
#pragma unroll
        for (int c = 0; c < 4; c++) acc[r][c] = 0.f;

    for (int k0 = 0; k0 < D_; k0 += BK) {
        float4 a4 = *(const float4*)(A + (size_t)(i0 + lr) * D_ + k0 + lk);
        float4 b4 = *(const float4*)(A + (size_t)(j0 + lr) * D_ + k0 + lk);
        As[lk + 0][lr] = a4.x; As[lk + 1][lr] = a4.y; As[lk + 2][lr] = a4.z; As[lk + 3][lr] = a4.w;
        Bs[lk + 0][lr] = b4.x; Bs[lk + 1][lr] = b4.y; Bs[lk + 2][lr] = b4.z; Bs[lk + 3][lr] = b4.w;
        __syncthreads();
#pragma unroll
        for (int k = 0; k < BK; k++) {
            float4 av = *(const float4*)&As[k][ty * 4];
            float4 bv = *(const float4*)&Bs[k][tx * 4];
            float ar[4] = {av.x, av.y, av.z, av.w};
            float br[4] = {bv.x, bv.y, bv.z, bv.w};
#pragma unroll
            for (int r = 0; r < 4; r++)
#pragma unroll
                for (int c = 0; c < 4; c++) acc[r][c] = fmaf(ar[r], br[c], acc[r][c]);
        }
        __syncthreads();
    }

    const float scale = 0.036084391824351615f;  // 1/sqrt(768)
#pragma unroll
    for (int r = 0; r < 4; r++) {
        float4 o;
        o.x = acc[r][0] * scale; o.y = acc[r][1] * scale;
        o.z = acc[r][2] * scale; o.w = acc[r][3] * scale;
        *(float4*)(C + (size_t)(i0 + ty * 4 + r) * T_ + j0 + tx * 4) = o;
    }
}

// ---------------------------------------------------------------------------
// Kernel 2: in-place causal softmax over j<=i, then zero by sit_mask outer
// product (post-softmax, no renorm). Writes zeros for j>i and masked rows.
// ---------------------------------------------------------------------------
__global__ __launch_bounds__(256) void softmax_kernel(const float* __restrict__ mask) {
    int row = blockIdx.x;
    int b = row >> 11;       // /T_
    int i = row & (T_ - 1);
    float* srow = g_S + (size_t)b * T_ * T_ + (size_t)i * T_;
    const float* mrow = mask + (size_t)b * T_;
    int tid = threadIdx.x;

    __shared__ float sh[T_];
    __shared__ float red[8];

    float maski = mrow[i];
    if (maski == 0.0f) {
        float4 z = make_float4(0.f, 0.f, 0.f, 0.f);
        for (int j4 = tid; j4 < T_ / 4; j4 += 256) ((float4*)srow)[j4] = z;
        return;
    }

    int n = i + 1;
    float lm = -3.4e38f;
    for (int j = tid; j < n; j += 256) { float v = srow[j]; sh[j] = v; lm = fmaxf(lm, v); }
#pragma unroll
    for (int o = 16; o > 0; o >>= 1) lm = fmaxf(lm, __shfl_xor_sync(0xffffffffu, lm, o));
    if ((tid & 31) == 0) red[tid >> 5] = lm;
    __syncthreads();
    float m = red[0];
#pragma unroll
    for (int k = 1; k < 8; k++) m = fmaxf(m, red[k]);
    __syncthreads();

    float ls = 0.f;
    for (int j = tid; j < n; j += 256) ls += __expf(sh[j] - m);
#pragma unroll
    for (int o = 16; o > 0; o >>= 1) ls += __shfl_xor_sync(0xffffffffu, ls, o);
    if ((tid & 31) == 0) red[tid >> 5] = ls;
    __syncthreads();
    float l = red[0];
#pragma unroll
    for (int k = 1; k < 8; k++) l += red[k];
    float inv = 1.0f / l;

    for (int j = tid; j < T_; j += 256) {
        float w = 0.f;
        if (j < n && mrow[j] != 0.f) w = __expf(sh[j] - m) * inv;
        srow[j] = w;
    }
}

// ---------------------------------------------------------------------------
// Kernel 3: out[b,i,0:D] = W[b,i,:] @ X[b,:,:]  (K-loop truncated at i0+BM
// since W is zero above the diagonal), out[b,i,D:2D] = X[b,i,:]  (concat).
// ---------------------------------------------------------------------------
__global__ __launch_bounds__(256) void pv_kernel(const float* __restrict__ X,
                                                 float* __restrict__ out) {
    int b  = blockIdx.z;
    int i0 = blockIdx.y * BM;
    int d0 = blockIdx.x * BN;

    const float* Wm = g_S + (size_t)b * T_ * T_;
    const float* Xb = X + (size_t)b * T_ * D_;

    __shared__ float As[BK][BM];
    __shared__ float Bs[BK][BN];

    int tid = threadIdx.x;
    int ty = tid >> 4, tx = tid & 15;
    int lr = tid >> 2;
    int lk = (tid & 3) << 2;
    int jb = tid >> 4;            // 0..15
    int dc = (tid & 15) << 2;     // 0..60

    float acc[4][4];
#pragma unroll
    for (int r = 0; r < 4; r++)
#pragma unroll
        for (int c = 0; c < 4; c++) acc[r][c] = 0.f;

    int kend = i0 + BM;  // W[i, j>i] == 0, so only k < i0+BM contributes
    for (int k0 = 0; k0 < kend; k0 += BK) {
        float4 a4 = *(const float4*)(Wm + (size_t)(i0 + lr) * T_ + k0 + lk);
        As[lk + 0][lr] = a4.x; As[lk + 1][lr] = a4.y; As[lk + 2][lr] = a4.z; As[lk + 3][lr] = a4.w;
        float4 b4 = *(const float4*)(Xb + (size_t)(k0 + jb) * D_ + d0 + dc);
        *(float4*)&Bs[jb][dc] = b4;
        __syncthreads();
#pragma unroll
        for (int k = 0; k < BK; k++) {
            float4 av = *(const float4*)&As[k][ty * 4];
            float4 bv = *(const float4*)&Bs[k][tx * 4];
            float ar[4] = {av.x, av.y, av.z, av.w};
            float br[4] = {bv.x, bv.y, bv.z, bv.w};
#pragma unroll
            for (int r = 0; r < 4; r++)
#pragma unroll
                for (int c = 0; c < 4; c++) acc[r][c] = fmaf(ar[r], br[c], acc[r][c]);
        }
        __syncthreads();
    }

#pragma unroll
    for (int r = 0; r < 4; r++) {
        int i = i0 + ty * 4 + r;
        float4 o;
        o.x = acc[r][0]; o.y = acc[r][1]; o.z = acc[r][2]; o.w = acc[r][3];
        *(float4*)(out + ((size_t)b * T_ + i) * (2 * D_) + d0 + tx * 4) = o;
        // concat copy of self hidden (free ride on this block's (i,d) coverage)
        float4 xv = *(const float4*)(Xb + (size_t)i * D_ + d0 + tx * 4);
        *(float4*)(out + ((size_t)b * T_ + i) * (2 * D_) + D_ + d0 + tx * 4) = xv;
    }
}

extern "C" void kernel_launch(void* const* d_in, const int* in_sizes, int n_in,
                              void* d_out, int out_size) {
    const float* X    = (const float*)d_in[0];
    const float* mask = (const float*)d_in[1];
    // d_in[2] (proposition_matrix) is unused by the reference computation.
    float* out = (float*)d_out;

    dim3 g1(T_ / BN, T_ / BM, B_);
    qk_kernel<<<g1, 256>>>(X);

    softmax_kernel<<<B_ * T_, 256>>>(mask);

    dim3 g3(D_ / BN, T_ / BM, B_);
    pv_kernel<<<g3, 256>>>(X, out);
}

// round 5
// speedup vs baseline: 2.6348x; 2.6348x over previous
#include <cuda_runtime.h>
#include <cuda.h>
#include <stdint.h>
#include <math.h>

#define B_ 8
#define T_ 2048
#define D_ 768
#define BK 32
#define LDS_ 36                     // padded row stride (floats): conflict-free frags
#define TILE_FLOATS (128 * LDS_)    // 4608 floats per operand tile
#define SMEM_DYN (2 * TILE_FLOATS * 4)  // A + B, 36864 B

// Scratch: scores -> (in-place) weights, plus transposed X.
__device__ float g_S[(size_t)B_ * T_ * T_];
__device__ float g_Xt[(size_t)B_ * D_ * T_];

__device__ __forceinline__ uint32_t f2tf32(float v) {
    uint32_t o;
    asm("cvt.rna.tf32.f32 %0, %1;" : "=r"(o) : "f"(v));
    return o;
}

__device__ __forceinline__ void mma_tf32(float& c0, float& c1, float& c2, float& c3,
                                         uint32_t a0, uint32_t a1, uint32_t a2, uint32_t a3,
                                         uint32_t b0, uint32_t b1) {
    asm volatile(
        "mma.sync.aligned.m16n8k8.row.col.f32.tf32.tf32.f32 "
        "{%0,%1,%2,%3}, {%4,%5,%6,%7}, {%8,%9}, {%0,%1,%2,%3};"
        : "+f"(c0), "+f"(c1), "+f"(c2), "+f"(c3)
        : "r"(a0), "r"(a1), "r"(a2), "r"(a3), "r"(b0), "r"(b1));
}

// ---------------------------------------------------------------------------
// Core warp-tile GEMM: C(128x128) += A(128xK) * B(128xK)^T, operands K-major
// fp32 in GMEM (rounded to tf32 at SMEM fill). 256 threads, 8 warps in 4x2,
// warp tile 32x64 -> 2 m-frags x 8 n-frags of m16n8k8.
// acc layout: acc[m][n][4]
// ---------------------------------------------------------------------------
struct Frag { float c[2][8][4]; };

__device__ __forceinline__ void gemm_chunk(const float* __restrict__ A, int lda,
                                           const float* __restrict__ Bp, int ldb,
                                           int k0, uint32_t* sA, uint32_t* sB,
                                           Frag& fr) {
    int tid = threadIdx.x;
    int row = tid >> 3;        // 0..31
    int f4 = tid & 7;          // float4 index within 32-float chunk row

#pragma unroll
    for (int p = 0; p < 4; p++) {
        int r = row + p * 32;
        float4 va = *(const float4*)(A + (size_t)r * lda + k0 + f4 * 4);
        float4 vb = *(const float4*)(Bp + (size_t)r * ldb + k0 + f4 * 4);
        uint32_t* da = sA + r * LDS_ + f4 * 4;
        uint32_t* db = sB + r * LDS_ + f4 * 4;
        da[0] = f2tf32(va.x); da[1] = f2tf32(va.y); da[2] = f2tf32(va.z); da[3] = f2tf32(va.w);
        db[0] = f2tf32(vb.x); db[1] = f2tf32(vb.y); db[2] = f2tf32(vb.z); db[3] = f2tf32(vb.w);
    }
    __syncthreads();

    int wid = tid >> 5, lane = tid & 31;
    int wr = (wid >> 1) * 32;    // warp row offset
    int wc = (wid & 1) * 64;     // warp col offset
    int g = lane >> 2, tg = lane & 3;

#pragma unroll
    for (int ks = 0; ks < 4; ks++) {
        int kc = ks * 8;
        uint32_t a[2][4];
#pragma unroll
        for (int m = 0; m < 2; m++) {
            int r0 = wr + m * 16 + g;
            a[m][0] = sA[r0 * LDS_ + kc + tg];
            a[m][1] = sA[(r0 + 8) * LDS_ + kc + tg];
            a[m][2] = sA[r0 * LDS_ + kc + tg + 4];
            a[m][3] = sA[(r0 + 8) * LDS_ + kc + tg + 4];
        }
#pragma unroll
        for (int n = 0; n < 8; n++) {
            int cn = wc + n * 8 + g;
            uint32_t b0 = sB[cn * LDS_ + kc + tg];
            uint32_t b1 = sB[cn * LDS_ + kc + tg + 4];
#pragma unroll
            for (int m = 0; m < 2; m++)
                mma_tf32(fr.c[m][n][0], fr.c[m][n][1], fr.c[m][n][2], fr.c[m][n][3],
                         a[m][0], a[m][1], a[m][2], a[m][3], b0, b1);
        }
    }
    __syncthreads();
}

// ---------------------------------------------------------------------------
// Kernel 1: S[b,i,j] = X[b,i,:].X[b,j,:] / sqrt(D)  (lower-triangle tiles only)
// ---------------------------------------------------------------------------
__global__ void __launch_bounds__(256) qk_mma_kernel(const float* __restrict__ X) {
    int b = blockIdx.z;
    int i0 = blockIdx.y * 128;
    int j0 = blockIdx.x * 128;
    if (j0 > i0) return;

    extern __shared__ uint32_t sm[];
    uint32_t* sA = sm;
    uint32_t* sB = sm + TILE_FLOATS;

    const float* A = X + (size_t)b * T_ * D_ + (size_t)i0 * D_;
    const float* Bp = X + (size_t)b * T_ * D_ + (size_t)j0 * D_;

    Frag fr;
#pragma unroll
    for (int m = 0; m < 2; m++)
#pragma unroll
        for (int n = 0; n < 8; n++)
#pragma unroll
            for (int q = 0; q < 4; q++) fr.c[m][n][q] = 0.f;

    for (int k0 = 0; k0 < D_; k0 += BK)
        gemm_chunk(A, D_, Bp, D_, k0, sA, sB, fr);

    int tid = threadIdx.x, wid = tid >> 5, lane = tid & 31;
    int wr = (wid >> 1) * 32, wc = (wid & 1) * 64;
    int g = lane >> 2, tg = lane & 3;
    const float scl = 0.036084391824351615f;  // 1/sqrt(768)
    float* C = g_S + (size_t)b * T_ * T_;
#pragma unroll
    for (int m = 0; m < 2; m++) {
        int r0 = i0 + wr + m * 16 + g;
#pragma unroll
        for (int n = 0; n < 8; n++) {
            int cc = j0 + wc + n * 8 + tg * 2;
            float2 v0 = make_float2(fr.c[m][n][0] * scl, fr.c[m][n][1] * scl);
            float2 v1 = make_float2(fr.c[m][n][2] * scl, fr.c[m][n][3] * scl);
            *(float2*)(C + (size_t)r0 * T_ + cc) = v0;
            *(float2*)(C + (size_t)(r0 + 8) * T_ + cc) = v1;
        }
    }
}

// ---------------------------------------------------------------------------
// Kernel 2: in-place causal softmax + post-softmax sit_mask zeroing
// ---------------------------------------------------------------------------
__global__ __launch_bounds__(256) void softmax_kernel(const float* __restrict__ mask) {
    int row = blockIdx.x;
    int b = row >> 11;
    int i = row & (T_ - 1);
    float* srow = g_S + (size_t)b * T_ * T_ + (size_t)i * T_;
    const float* mrow = mask + (size_t)b * T_;
    int tid = threadIdx.x;

    __shared__ float sh[T_];
    __shared__ float red[8];

    if (mrow[i] == 0.0f) {
        float4 z = make_float4(0.f, 0.f, 0.f, 0.f);
        for (int j4 = tid; j4 < T_ / 4; j4 += 256) ((float4*)srow)[j4] = z;
        return;
    }

    int n = i + 1;
    float lm = -3.4e38f;
    for (int j = tid; j < n; j += 256) { float v = srow[j]; sh[j] = v; lm = fmaxf(lm, v); }
#pragma unroll
    for (int o = 16; o > 0; o >>= 1) lm = fmaxf(lm, __shfl_xor_sync(0xffffffffu, lm, o));
    if ((tid & 31) == 0) red[tid >> 5] = lm;
    __syncthreads();
    float m = red[0];
#pragma unroll
    for (int k = 1; k < 8; k++) m = fmaxf(m, red[k]);
    __syncthreads();

    float ls = 0.f;
    for (int j = tid; j < n; j += 256) ls += __expf(sh[j] - m);
#pragma unroll
    for (int o = 16; o > 0; o >>= 1) ls += __shfl_xor_sync(0xffffffffu, ls, o);
    if ((tid & 31) == 0) red[tid >> 5] = ls;
    __syncthreads();
    float l = red[0];
#pragma unroll
    for (int k = 1; k < 8; k++) l += red[k];
    float inv = 1.0f / l;

    for (int j = tid; j < T_; j += 256) {
        float w = 0.f;
        if (j < n && mrow[j] != 0.f) w = __expf(sh[j] - m) * inv;
        srow[j] = w;
    }
}

// ---------------------------------------------------------------------------
// Kernel 2.5: Xt[b,d,j] = X[b,j,d]; also writes concat half out[b,j,D+d]
// ---------------------------------------------------------------------------
__global__ __launch_bounds__(256) void transpose_concat_kernel(const float* __restrict__ X,
                                                               float* __restrict__ out) {
    __shared__ float t[32][33];
    int b = blockIdx.z, j0 = blockIdx.x * 32, d0 = blockIdx.y * 32;
    int tx = threadIdx.x, ty = threadIdx.y;
    const float* Xb = X + (size_t)b * T_ * D_;
#pragma unroll
    for (int r = 0; r < 32; r += 8) {
        float v = Xb[(size_t)(j0 + ty + r) * D_ + d0 + tx];
        t[ty + r][tx] = v;
        out[((size_t)b * T_ + j0 + ty + r) * (2 * D_) + D_ + d0 + tx] = v;
    }
    __syncthreads();
    float* Xt = g_Xt + (size_t)b * D_ * T_;
#pragma unroll
    for (int r = 0; r < 32; r += 8)
        Xt[(size_t)(d0 + ty + r) * T_ + j0 + tx] = t[tx][ty + r];
}

// ---------------------------------------------------------------------------
// Kernel 3: out[b,i,d] = sum_j W[b,i,j]*Xt[b,d,j]  (K truncated at i0+128)
// ---------------------------------------------------------------------------
__global__ void __launch_bounds__(256) pv_mma_kernel(float* __restrict__ out) {
    int b = blockIdx.z;
    int i0 = blockIdx.y * 128;
    int d0 = blockIdx.x * 128;

    extern __shared__ uint32_t sm[];
    uint32_t* sA = sm;
    uint32_t* sB = sm + TILE_FLOATS;

    const float* A = g_S + (size_t)b * T_ * T_ + (size_t)i0 * T_;
    const float* Bp = g_Xt + (size_t)b * D_ * T_ + (size_t)d0 * T_;

    Frag fr;
#pragma unroll
    for (int m = 0; m < 2; m++)
#pragma unroll
        for (int n = 0; n < 8; n++)
#pragma unroll
            for (int q = 0; q < 4; q++) fr.c[m][n][q] = 0.f;

    int kend = i0 + 128;  // W[i, j > i] == 0
    for (int k0 = 0; k0 < kend; k0 += BK)
        gemm_chunk(A, T_, Bp, T_, k0, sA, sB, fr);

    int tid = threadIdx.x, wid = tid >> 5, lane = tid & 31;
    int wr = (wid >> 1) * 32, wc = (wid & 1) * 64;
    int g = lane >> 2, tg = lane & 3;
#pragma unroll
    for (int m = 0; m < 2; m++) {
        int r0 = i0 + wr + m * 16 + g;
#pragma unroll
        for (int n = 0; n < 8; n++) {
            int cc = d0 + wc + n * 8 + tg * 2;
            float2 v0 = make_float2(fr.c[m][n][0], fr.c[m][n][1]);
            float2 v1 = make_float2(fr.c[m][n][2], fr.c[m][n][3]);
            *(float2*)(out + ((size_t)b * T_ + r0) * (2 * D_) + cc) = v0;
            *(float2*)(out + ((size_t)b * T_ + r0 + 8) * (2 * D_) + cc) = v1;
        }
    }
}

extern "C" void kernel_launch(void* const* d_in, const int* in_sizes, int n_in,
                              void* d_out, int out_size) {
    const float* X = (const float*)d_in[0];
    const float* mask = (const float*)d_in[1];
    // d_in[2] (proposition_matrix) is unused by the reference computation.
    float* out = (float*)d_out;

    cudaFuncSetAttribute(qk_mma_kernel, cudaFuncAttributeMaxDynamicSharedMemorySize, SMEM_DYN);
    cudaFuncSetAttribute(pv_mma_kernel, cudaFuncAttributeMaxDynamicSharedMemorySize, SMEM_DYN);

    dim3 gt(T_ / 32, D_ / 32, B_);
    transpose_concat_kernel<<<gt, dim3(32, 8)>>>(X, out);

    dim3 g1(T_ / 128, T_ / 128, B_);
    qk_mma_kernel<<<g1, 256, SMEM_DYN>>>(X);

    softmax_kernel<<<B_ * T_, 256>>>(mask);

    dim3 g3(D_ / 128, T_ / 128, B_);
    pv_mma_kernel<<<g3, 256, SMEM_DYN>>>(out);
}

// round 6
// speedup vs baseline: 3.0609x; 1.1617x over previous
#include <cuda_runtime.h>
#include <cuda.h>
#include <stdint.h>
#include <math.h>

#define B_ 8
#define T_ 2048
#define D_ 768
#define KC 32
#define LDS_ 36                       // padded row stride (floats): conflict-free frags
#define TILE_FLOATS (128 * LDS_)      // 4608 floats per operand tile
#define SMEM_DYN (4 * TILE_FLOATS * 4)  // 2 stages x (A + B) = 73728 B

// Scratch: scores->(in-place) weights; transposed tf32 X; converted row-major X.
__device__ float g_S[(size_t)B_ * T_ * T_];
__device__ float g_Xt[(size_t)B_ * D_ * T_];
__device__ float g_Xc[(size_t)B_ * T_ * D_];

__device__ __forceinline__ uint32_t f2tf32(float v) {
    uint32_t o;
    asm("cvt.rna.tf32.f32 %0, %1;" : "=r"(o) : "f"(v));
    return o;
}

__device__ __forceinline__ void mma_tf32(float& c0, float& c1, float& c2, float& c3,
                                         uint32_t a0, uint32_t a1, uint32_t a2, uint32_t a3,
                                         uint32_t b0, uint32_t b1) {
    asm volatile(
        "mma.sync.aligned.m16n8k8.row.col.f32.tf32.tf32.f32 "
        "{%0,%1,%2,%3}, {%4,%5,%6,%7}, {%8,%9}, {%0,%1,%2,%3};"
        : "+f"(c0), "+f"(c1), "+f"(c2), "+f"(c3)
        : "r"(a0), "r"(a1), "r"(a2), "r"(a3), "r"(b0), "r"(b1));
}

struct Frag { float c[2][8][4]; };

// ---------------------------------------------------------------------------
// cp.async producer: one 128x32 fp32 chunk of each operand into stage st.
// Data in GMEM is already tf32-rounded, so a raw byte copy preserves numerics.
// ---------------------------------------------------------------------------
__device__ __forceinline__ void issue_chunk(const float* __restrict__ A, int lda,
                                            const float* __restrict__ Bp, int ldb,
                                            int k0, uint32_t sA, uint32_t sB) {
    int tid = threadIdx.x;
    int row = tid >> 3, f4 = tid & 7;
#pragma unroll
    for (int p = 0; p < 4; p++) {
        int r = row + p * 32;
        const float* ga = A + (size_t)r * lda + k0 + f4 * 4;
        const float* gb = Bp + (size_t)r * ldb + k0 + f4 * 4;
        uint32_t da = sA + (uint32_t)(r * LDS_ + f4 * 4) * 4u;
        uint32_t db = sB + (uint32_t)(r * LDS_ + f4 * 4) * 4u;
        asm volatile("cp.async.cg.shared.global [%0], [%1], 16;" :: "r"(da), "l"(ga));
        asm volatile("cp.async.cg.shared.global [%0], [%1], 16;" :: "r"(db), "l"(gb));
    }
    asm volatile("cp.async.commit_group;" ::: "memory");
}

// ---------------------------------------------------------------------------
// MMA consumer for one staged chunk.
// ---------------------------------------------------------------------------
__device__ __forceinline__ void compute_chunk(const uint32_t* __restrict__ sA,
                                              const uint32_t* __restrict__ sB,
                                              Frag& fr) {
    int tid = threadIdx.x, wid = tid >> 5, lane = tid & 31;
    int wr = (wid >> 1) * 32;
    int wc = (wid & 1) * 64;
    int g = lane >> 2, tg = lane & 3;

#pragma unroll
    for (int ks = 0; ks < 4; ks++) {
        int kc = ks * 8;
        uint32_t a[2][4];
#pragma unroll
        for (int m = 0; m < 2; m++) {
            int r0 = wr + m * 16 + g;
            a[m][0] = sA[r0 * LDS_ + kc + tg];
            a[m][1] = sA[(r0 + 8) * LDS_ + kc + tg];
            a[m][2] = sA[r0 * LDS_ + kc + tg + 4];
            a[m][3] = sA[(r0 + 8) * LDS_ + kc + tg + 4];
        }
#pragma unroll
        for (int n = 0; n < 8; n++) {
            int cn = wc + n * 8 + g;
            uint32_t b0 = sB[cn * LDS_ + kc + tg];
            uint32_t b1 = sB[cn * LDS_ + kc + tg + 4];
#pragma unroll
            for (int m = 0; m < 2; m++)
                mma_tf32(fr.c[m][n][0], fr.c[m][n][1], fr.c[m][n][2], fr.c[m][n][3],
                         a[m][0], a[m][1], a[m][2], a[m][3], b0, b1);
        }
    }
}

// ---------------------------------------------------------------------------
// Double-buffered GEMM mainloop: C(128x128) += A(128xK) * B(128xK)^T.
// ---------------------------------------------------------------------------
__device__ __forceinline__ void run_gemm(const float* __restrict__ A, int lda,
                                         const float* __restrict__ Bp, int ldb,
                                         int nchunks, uint32_t* sm, Frag& fr) {
#pragma unroll
    for (int m = 0; m < 2; m++)
#pragma unroll
        for (int n = 0; n < 8; n++)
#pragma unroll
            for (int q = 0; q < 4; q++) fr.c[m][n][q] = 0.f;

    uint32_t sbase = (uint32_t)__cvta_generic_to_shared(sm);
    uint32_t stA[2] = { sbase, sbase + 2u * TILE_FLOATS * 4u };
    uint32_t stB[2] = { sbase + TILE_FLOATS * 4u, sbase + 3u * TILE_FLOATS * 4u };
    const uint32_t* cA[2] = { sm, sm + 2 * TILE_FLOATS };
    const uint32_t* cB[2] = { sm + TILE_FLOATS, sm + 3 * TILE_FLOATS };

    issue_chunk(A, lda, Bp, ldb, 0, stA[0], stB[0]);
    for (int c = 0; c < nchunks; c++) {
        if (c + 1 < nchunks) {
            issue_chunk(A, lda, Bp, ldb, (c + 1) * KC, stA[(c + 1) & 1], stB[(c + 1) & 1]);
            asm volatile("cp.async.wait_group 1;" ::: "memory");
        } else {
            asm volatile("cp.async.wait_group 0;" ::: "memory");
        }
        __syncthreads();
        compute_chunk(cA[c & 1], cB[c & 1], fr);
        __syncthreads();
    }
}

// ---------------------------------------------------------------------------
// Kernel 1: S[b,i,j] = Xc[b,i,:].Xc[b,j,:] / sqrt(D)  (lower-triangle tiles)
// ---------------------------------------------------------------------------
__global__ void __launch_bounds__(256) qk_mma_kernel() {
    int b = blockIdx.z;
    int i0 = blockIdx.y * 128;
    int j0 = blockIdx.x * 128;
    if (j0 > i0) return;

    extern __shared__ uint32_t sm[];
    const float* A = g_Xc + (size_t)b * T_ * D_ + (size_t)i0 * D_;
    const float* Bp = g_Xc + (size_t)b * T_ * D_ + (size_t)j0 * D_;

    Frag fr;
    run_gemm(A, D_, Bp, D_, D_ / KC, sm, fr);

    int tid = threadIdx.x, wid = tid >> 5, lane = tid & 31;
    int wr = (wid >> 1) * 32, wc = (wid & 1) * 64;
    int g = lane >> 2, tg = lane & 3;
    const float scl = 0.036084391824351615f;  // 1/sqrt(768)
    float* C = g_S + (size_t)b * T_ * T_;
#pragma unroll
    for (int m = 0; m < 2; m++) {
        int r0 = i0 + wr + m * 16 + g;
#pragma unroll
        for (int n = 0; n < 8; n++) {
            int cc = j0 + wc + n * 8 + tg * 2;
            float2 v0 = make_float2(fr.c[m][n][0] * scl, fr.c[m][n][1] * scl);
            float2 v1 = make_float2(fr.c[m][n][2] * scl, fr.c[m][n][3] * scl);
            *(float2*)(C + (size_t)r0 * T_ + cc) = v0;
            *(float2*)(C + (size_t)(r0 + 8) * T_ + cc) = v1;
        }
    }
}

// ---------------------------------------------------------------------------
// Kernel 2: in-place causal softmax + post-softmax sit_mask zeroing.
// Weights are tf32-rounded at the store so pv can cp.async raw bytes.
// ---------------------------------------------------------------------------
__global__ __launch_bounds__(256) void softmax_kernel(const float* __restrict__ mask) {
    int row = blockIdx.x;
    int b = row >> 11;
    int i = row & (T_ - 1);
    float* srow = g_S + (size_t)b * T_ * T_ + (size_t)i * T_;
    const float* mrow = mask + (size_t)b * T_;
    int tid = threadIdx.x;

    __shared__ float sh[T_];
    __shared__ float red[8];

    if (mrow[i] == 0.0f) {
        float4 z = make_float4(0.f, 0.f, 0.f, 0.f);
        for (int j4 = tid; j4 < T_ / 4; j4 += 256) ((float4*)srow)[j4] = z;
        return;
    }

    int n = i + 1;
    float lm = -3.4e38f;
    for (int j = tid; j < n; j += 256) { float v = srow[j]; sh[j] = v; lm = fmaxf(lm, v); }
#pragma unroll
    for (int o = 16; o > 0; o >>= 1) lm = fmaxf(lm, __shfl_xor_sync(0xffffffffu, lm, o));
    if ((tid & 31) == 0) red[tid >> 5] = lm;
    __syncthreads();
    float m = red[0];
#pragma unroll
    for (int k = 1; k < 8; k++) m = fmaxf(m, red[k]);
    __syncthreads();

    float ls = 0.f;
    for (int j = tid; j < n; j += 256) ls += __expf(sh[j] - m);
#pragma unroll
    for (int o = 16; o > 0; o >>= 1) ls += __shfl_xor_sync(0xffffffffu, ls, o);
    if ((tid & 31) == 0) red[tid >> 5] = ls;
    __syncthreads();
    float l = red[0];
#pragma unroll
    for (int k = 1; k < 8; k++) l += red[k];
    float inv = 1.0f / l;

    for (int j = tid; j < T_; j += 256) {
        float w = 0.f;
        if (j < n && mrow[j] != 0.f) w = __expf(sh[j] - m) * inv;
        srow[j] = __uint_as_float(f2tf32(w));
    }
}

// ---------------------------------------------------------------------------
// Kernel 2.5: Xt[b,d,j] = tf32(X[b,j,d]); Xc[b,j,d] = tf32(X[b,j,d]);
//             out[b,j,D+d] = X[b,j,d]  (concat half, unconverted)
// ---------------------------------------------------------------------------
__global__ __launch_bounds__(256) void transpose_concat_kernel(const float* __restrict__ X,
                                                               float* __restrict__ out) {
    __shared__ float t[32][33];
    int b = blockIdx.z, j0 = blockIdx.x * 32, d0 = blockIdx.y * 32;
    int tx = threadIdx.x, ty = threadIdx.y;
    const float* Xb = X + (size_t)b * T_ * D_;
    float* Xc = g_Xc + (size_t)b * T_ * D_;
#pragma unroll
    for (int r = 0; r < 32; r += 8) {
        float v = Xb[(size_t)(j0 + ty + r) * D_ + d0 + tx];
        float vt = __uint_as_float(f2tf32(v));
        t[ty + r][tx] = vt;
        out[((size_t)b * T_ + j0 + ty + r) * (2 * D_) + D_ + d0 + tx] = v;
        Xc[(size_t)(j0 + ty + r) * D_ + d0 + tx] = vt;
    }
    __syncthreads();
    float* Xt = g_Xt + (size_t)b * D_ * T_;
#pragma unroll
    for (int r = 0; r < 32; r += 8)
        Xt[(size_t)(d0 + ty + r) * T_ + j0 + tx] = t[tx][ty + r];
}

// ---------------------------------------------------------------------------
// Kernel 3: out[b,i,d] = sum_j W[b,i,j]*Xt[b,d,j]  (K truncated at i0+128)
// ---------------------------------------------------------------------------
__global__ void __launch_bounds__(256) pv_mma_kernel(float* __restrict__ out) {
    int b = blockIdx.z;
    int i0 = blockIdx.y * 128;
    int d0 = blockIdx.x * 128;

    extern __shared__ uint32_t sm[];
    const float* A = g_S + (size_t)b * T_ * T_ + (size_t)i0 * T_;
    const float* Bp = g_Xt + (size_t)b * D_ * T_ + (size_t)d0 * T_;

    Frag fr;
    run_gemm(A, T_, Bp, T_, (i0 + 128) / KC, sm, fr);

    int tid = threadIdx.x, wid = tid >> 5, lane = tid & 31;
    int wr = (wid >> 1) * 32, wc = (wid & 1) * 64;
    int g = lane >> 2, tg = lane & 3;
#pragma unroll
    for (int m = 0; m < 2; m++) {
        int r0 = i0 + wr + m * 16 + g;
#pragma unroll
        for (int n = 0; n < 8; n++) {
            int cc = d0 + wc + n * 8 + tg * 2;
            float2 v0 = make_float2(fr.c[m][n][0], fr.c[m][n][1]);
            float2 v1 = make_float2(fr.c[m][n][2], fr.c[m][n][3]);
            *(float2*)(out + ((size_t)b * T_ + r0) * (2 * D_) + cc) = v0;
            *(float2*)(out + ((size_t)b * T_ + r0 + 8) * (2 * D_) + cc) = v1;
        }
    }
}

extern "C" void kernel_launch(void* const* d_in, const int* in_sizes, int n_in,
                              void* d_out, int out_size) {
    const float* X = (const float*)d_in[0];
    const float* mask = (const float*)d_in[1];
    // d_in[2] (proposition_matrix) is unused by the reference computation.
    float* out = (float*)d_out;

    cudaFuncSetAttribute(qk_mma_kernel, cudaFuncAttributeMaxDynamicSharedMemorySize, SMEM_DYN);
    cudaFuncSetAttribute(pv_mma_kernel, cudaFuncAttributeMaxDynamicSharedMemorySize, SMEM_DYN);

    dim3 gt(T_ / 32, D_ / 32, B_);
    transpose_concat_kernel<<<gt, dim3(32, 8)>>>(X, out);

    dim3 g1(T_ / 128, T_ / 128, B_);
    qk_mma_kernel<<<g1, 256, SMEM_DYN>>>();

    softmax_kernel<<<B_ * T_, 256>>>(mask);

    dim3 g3(D_ / 128, T_ / 128, B_);
    pv_mma_kernel<<<g3, 256, SMEM_DYN>>>(out);
}